// round 3
// baseline (speedup 1.0000x reference)
#include <cuda_runtime.h>
#include <math.h>

#define NT 256

// ---------------- device scratch (no allocation allowed) ----------------
__device__ __align__(16) float g_geo[64*64];
__device__ __align__(16) float g_wq[64*64];
__device__ __align__(16) float g_wk[64*64];
__device__ __align__(16) float g_wv[64*64];
__device__ __align__(16) float g_bq[64];
__device__ __align__(16) float g_bk[64];
__device__ __align__(16) float g_bv[64];

// ---------------- prep: geo matrix + fused QKV weights ----------------
__global__ void esa_prep_kernel(const float* __restrict__ points,
                                const int*   __restrict__ adjacency,
                                const float* __restrict__ in_w,
                                const float* __restrict__ in_b,
                                const float* __restrict__ q_w, const float* __restrict__ q_b,
                                const float* __restrict__ k_w, const float* __restrict__ k_b,
                                const float* __restrict__ v_w, const float* __restrict__ v_b)
{
    const int gtid = blockIdx.x * blockDim.x + threadIdx.x;
    const int gstride = gridDim.x * blockDim.x;
    const float scale = 0.3535533905932738f; // 1/sqrt(8)

    for (int idx = gtid; idx < 4096; idx += gstride) {
        int n = idx >> 6, m = idx & 63;
        float dx = points[n*3+0] - points[m*3+0];
        float dy = points[n*3+1] - points[m*3+1];
        float dz = points[n*3+2] - points[m*3+2];
        float dist = sqrtf(dx*dx + dy*dy + dz*dz + 1e-12f);
        g_geo[idx] = (adjacency[idx] > 0) ? 0.5f : (-0.1f / (1.0f + dist));
    }
    // W_eff[o][u] = sum_t in_w[o][t] * x_w[t][u]   (q scaled by 1/sqrt(D))
    for (int idx = gtid; idx < 3*4096; idx += gstride) {
        int which = idx >> 12;
        int o = (idx >> 6) & 63;
        int u = idx & 63;
        const float* wi = in_w + which*4096 + o*64;
        const float* wx = (which==0) ? q_w : (which==1) ? k_w : v_w;
        float s = 0.f;
        #pragma unroll 4
        for (int t = 0; t < 64; t++) s += wi[t] * wx[t*64 + u];
        if (which == 0) s *= scale;
        float* dst = (which==0) ? g_wq : (which==1) ? g_wk : g_wv;
        dst[o*64 + u] = s;
    }
    // b_eff[o] = in_w[o]·x_b + in_b[o]
    for (int idx = gtid; idx < 192; idx += gstride) {
        int which = idx >> 6, o = idx & 63;
        const float* wi = in_w + which*4096 + o*64;
        const float* bx = (which==0) ? q_b : (which==1) ? k_b : v_b;
        float s = in_b[which*64 + o];
        for (int t = 0; t < 64; t++) s += wi[t] * bx[t];
        if (which == 0) s *= scale;
        float* dst = (which==0) ? g_bq : (which==1) ? g_bk : g_bv;
        dst[o] = s;
    }
}

// ---------------- main kernel helpers ----------------
// copy row-major (rows x K) weight into smem with padded stride SW (K%4==0)
__device__ __forceinline__ void load_w_pad(const float* __restrict__ g, float* __restrict__ s,
                                           int total, int K, int SW, int tid)
{
    for (int idx = tid*4; idx < total; idx += NT*4) {
        int r = idx / K;
        int c = idx - r*K;
        *(float4*)(s + r*SW + c) = __ldg((const float4*)(g + idx));
    }
}

// out[n][j] = (relu?)(bias[j] + sum_k in[n][k]*W[j][k]); n,j in [0,64)
// thread: 4 consecutive n rows, 4 j columns interleaved by 16 (bank-conflict-free)
template<int K, bool RELU>
__device__ __forceinline__ void gemm64(const float* __restrict__ in, int sin,
                                       const float* __restrict__ w,  int sw,
                                       const float* __restrict__ bias,
                                       float* __restrict__ out, int so, int tid)
{
    const int n0 = (tid >> 4) << 2;
    const int j0 = tid & 15;
    float acc[4][4];
    #pragma unroll
    for (int i = 0; i < 4; i++) { acc[i][0]=0.f; acc[i][1]=0.f; acc[i][2]=0.f; acc[i][3]=0.f; }
    #pragma unroll 2
    for (int k = 0; k < K; k += 4) {
        float4 a[4], b[4];
        #pragma unroll
        for (int i = 0; i < 4; i++) a[i] = *(const float4*)(in + (n0+i)*sin + k);
        #pragma unroll
        for (int j = 0; j < 4; j++) b[j] = *(const float4*)(w + (j0 + 16*j)*sw + k);
        #pragma unroll
        for (int i = 0; i < 4; i++)
            #pragma unroll
            for (int j = 0; j < 4; j++)
                acc[i][j] += a[i].x*b[j].x + a[i].y*b[j].y + a[i].z*b[j].z + a[i].w*b[j].w;
    }
    #pragma unroll
    for (int j = 0; j < 4; j++) {
        float bj = __ldg(bias + j0 + 16*j);
        #pragma unroll
        for (int i = 0; i < 4; i++) {
            float v = acc[i][j] + bj;
            if (RELU) v = fmaxf(v, 0.f);
            out[(n0+i)*so + j0 + 16*j] = v;
        }
    }
}

// attended = ctx@mo^T + mo_b + geo + pf  (K=64, strides 68)
__device__ __forceinline__ void gemm_mo(const float* __restrict__ in,
                                        const float* __restrict__ w,
                                        const float* __restrict__ mo_b,
                                        const float* __restrict__ pf,
                                        float* __restrict__ out, int tid)
{
    const int n0 = (tid >> 4) << 2;
    const int j0 = tid & 15;
    float acc[4][4];
    #pragma unroll
    for (int i = 0; i < 4; i++) { acc[i][0]=0.f; acc[i][1]=0.f; acc[i][2]=0.f; acc[i][3]=0.f; }
    #pragma unroll 2
    for (int k = 0; k < 64; k += 4) {
        float4 a[4], b[4];
        #pragma unroll
        for (int i = 0; i < 4; i++) a[i] = *(const float4*)(in + (n0+i)*68 + k);
        #pragma unroll
        for (int j = 0; j < 4; j++) b[j] = *(const float4*)(w + (j0 + 16*j)*68 + k);
        #pragma unroll
        for (int i = 0; i < 4; i++)
            #pragma unroll
            for (int j = 0; j < 4; j++)
                acc[i][j] += a[i].x*b[j].x + a[i].y*b[j].y + a[i].z*b[j].z + a[i].w*b[j].w;
    }
    #pragma unroll
    for (int j = 0; j < 4; j++) {
        int jj = j0 + 16*j;
        float bj = __ldg(mo_b + jj);
        #pragma unroll
        for (int i = 0; i < 4; i++) {
            int nn = n0 + i;
            out[nn*68 + jj] = acc[i][j] + bj + g_geo[nn*64 + jj] + pf[nn*68 + jj];
        }
    }
}

// ---------------- main fused kernel: one CTA per batch element ----------------
// smem regions (floats):
//   PF 0     (4352)  : pf, persistent residual
//   W  4352  (5376)  : staged weights / softmax probs
//   R1 9728  (4352)  : xs -> pm1 tmp -> K2 -> h/hn
//   PI 14080 (5376)  : pi (64x84) -> Q2
//   R2 19456 (4352)  : V2
//   R3 23808 (4352)  : ctx -> out(stride 65)
#define SMEM_FLOATS 28160

__global__ void __launch_bounds__(NT, 2)
esa_main_kernel(const float* __restrict__ x,
                const float* __restrict__ conv1_w, const float* __restrict__ conv1_b,
                const float* __restrict__ conv2_w, const float* __restrict__ conv2_b,
                const float* __restrict__ pattern,
                const float* __restrict__ pm1_w, const float* __restrict__ pm1_b,
                const float* __restrict__ pm2_w, const float* __restrict__ pm2_b,
                const float* __restrict__ mo_w,  const float* __restrict__ mo_b,
                const float* __restrict__ out_w, const float* __restrict__ out_b,
                const float* __restrict__ ln_g,  const float* __restrict__ ln_b,
                float* __restrict__ out)
{
    extern __shared__ float sm[];
    const int tid = threadIdx.x;
    const int b = blockIdx.x;
    float* PF = sm;
    float* W  = sm + 4352;
    float* R1 = sm + 9728;
    float* PI = sm + 14080;
    float* R2 = sm + 19456;
    float* R3 = sm + 23808;

    // ---- load x (C=64 rows, padded cols [0..65], stride 68) + pattern memory ----
    const float* xg = x + (size_t)b * 4096;
    for (int idx = tid; idx < 4096; idx += NT) {
        int c = idx >> 6, n = idx & 63;
        R1[c*68 + 1 + n] = xg[idx];
    }
    if (tid < 64) { R1[tid*68] = 0.f; R1[tid*68 + 65] = 0.f; }
    for (int idx = tid; idx < 1024; idx += NT) {
        int n = idx >> 4, p = idx & 15;
        PI[n*84 + 64 + p] = __ldg(pattern + idx);
    }
    __syncthreads();

    // ---- 4-scale conv stack; conv2 writes transposed into PI[:, s*16+o] ----
    float* Y1 = W + 3072; // 16 x 68 padded
    for (int s = 0; s < 4; s++) {
        const float* w1g = conv1_w + s*3072;
        for (int idx = tid*4; idx < 3072; idx += NT*4)
            *(float4*)(W + idx) = __ldg((const float4*)(w1g + idx));
        if (tid < 16) { Y1[tid*68] = 0.f; Y1[tid*68 + 65] = 0.f; }
        __syncthreads();
        {
            int o = tid >> 4, nq = tid & 15, base = nq*4;
            const float* wr = W + o*192;
            float a0=0.f, a1=0.f, a2=0.f, a3=0.f;
            #pragma unroll 8
            for (int c = 0; c < 64; c++) {
                float w0 = wr[c*3+0], ww1 = wr[c*3+1], ww2 = wr[c*3+2];
                const float* xr = R1 + c*68 + base;
                float4 xv = *(const float4*)xr;
                float2 x2 = *(const float2*)(xr + 4);
                a0 += w0*xv.x + ww1*xv.y + ww2*xv.z;
                a1 += w0*xv.y + ww1*xv.z + ww2*xv.w;
                a2 += w0*xv.z + ww1*xv.w + ww2*x2.x;
                a3 += w0*xv.w + ww1*x2.x + ww2*x2.y;
            }
            float bb = __ldg(conv1_b + s*16 + o);
            float* yr = Y1 + o*68 + 1 + base;
            yr[0] = fmaxf(a0+bb, 0.f); yr[1] = fmaxf(a1+bb, 0.f);
            yr[2] = fmaxf(a2+bb, 0.f); yr[3] = fmaxf(a3+bb, 0.f);
        }
        __syncthreads();
        const float* w2g = conv2_w + s*768;
        for (int idx = tid*4; idx < 768; idx += NT*4)
            *(float4*)(W + idx) = __ldg((const float4*)(w2g + idx));
        __syncthreads();
        {
            int o = tid >> 4, nq = tid & 15, base = nq*4;
            const float* wr = W + o*48;
            float a0=0.f, a1=0.f, a2=0.f, a3=0.f;
            #pragma unroll
            for (int c = 0; c < 16; c++) {
                float w0 = wr[c*3+0], ww1 = wr[c*3+1], ww2 = wr[c*3+2];
                const float* xr = Y1 + c*68 + base;
                float4 xv = *(const float4*)xr;
                float2 x2 = *(const float2*)(xr + 4);
                a0 += w0*xv.x + ww1*xv.y + ww2*xv.z;
                a1 += w0*xv.y + ww1*xv.z + ww2*xv.w;
                a2 += w0*xv.z + ww1*xv.w + ww2*x2.x;
                a3 += w0*xv.w + ww1*x2.x + ww2*x2.y;
            }
            float bb = __ldg(conv2_b + s*16 + o);
            int ch = s*16 + o;
            PI[(base+0)*84 + ch] = fmaxf(a0+bb, 0.f);
            PI[(base+1)*84 + ch] = fmaxf(a1+bb, 0.f);
            PI[(base+2)*84 + ch] = fmaxf(a2+bb, 0.f);
            PI[(base+3)*84 + ch] = fmaxf(a3+bb, 0.f);
        }
        __syncthreads();
    }

    // ---- pattern MLP: pf = relu(pi@pm1^T+b) @ pm2^T + b ----
    load_w_pad(pm1_w, W, 64*80, 80, 84, tid);
    __syncthreads();
    gemm64<80, true>(PI, 84, W, 84, pm1_b, R1, 68, tid);
    __syncthreads();
    load_w_pad(pm2_w, W, 4096, 64, 68, tid);
    __syncthreads();
    gemm64<64, false>(R1, 68, W, 68, pm2_b, PF, 68, tid);
    __syncthreads();

    // ---- fused Q2/K2/V2 (qkv + in_w collapsed, scale folded into Q) ----
    load_w_pad(g_wq, W, 4096, 64, 68, tid);
    __syncthreads();
    gemm64<64, false>(PF, 68, W, 68, g_bq, PI, 68, tid);   // Q2
    __syncthreads();
    load_w_pad(g_wk, W, 4096, 64, 68, tid);
    __syncthreads();
    gemm64<64, false>(PF, 68, W, 68, g_bk, R1, 68, tid);   // K2
    __syncthreads();
    load_w_pad(g_wv, W, 4096, 64, 68, tid);
    __syncthreads();
    gemm64<64, false>(PF, 68, W, 68, g_bv, R2, 68, tid);   // V2
    __syncthreads();

    // ---- attention: 8 heads, scores in registers, probs in SB=W ----
    float* Q2 = PI; float* K2 = R1; float* V2 = R2; float* CTX = R3; float* SB = W;
    for (int h = 0; h < 8; h++) {
        {
            int n = tid >> 2, g = tid & 3, m0 = g*16;
            const float* qr = Q2 + n*68 + h*8;
            float4 qa = *(const float4*)qr;
            float4 qb = *(const float4*)(qr + 4);
            float sc[16];
            float mx = -3.0e38f;
            #pragma unroll
            for (int mm = 0; mm < 16; mm++) {
                const float* kr = K2 + (m0+mm)*68 + h*8;
                float4 ka = *(const float4*)kr;
                float4 kb = *(const float4*)(kr + 4);
                float d = qa.x*ka.x + qa.y*ka.y + qa.z*ka.z + qa.w*ka.w
                        + qb.x*kb.x + qb.y*kb.y + qb.z*kb.z + qb.w*kb.w;
                sc[mm] = d; mx = fmaxf(mx, d);
            }
            mx = fmaxf(mx, __shfl_xor_sync(0xffffffffu, mx, 1));
            mx = fmaxf(mx, __shfl_xor_sync(0xffffffffu, mx, 2));
            float sum = 0.f;
            #pragma unroll
            for (int mm = 0; mm < 16; mm++) { float e = __expf(sc[mm]-mx); sc[mm] = e; sum += e; }
            sum += __shfl_xor_sync(0xffffffffu, sum, 1);
            sum += __shfl_xor_sync(0xffffffffu, sum, 2);
            float inv = 1.f / sum;
            #pragma unroll
            for (int mm = 0; mm < 16; mm++) SB[n*64 + m0 + mm] = sc[mm] * inv;
        }
        __syncthreads();
        {
            int n2 = tid >> 2, dg = tid & 3, d0 = h*8 + dg*2;
            float a0 = 0.f, a1 = 0.f;
            #pragma unroll 4
            for (int m = 0; m < 64; m++) {
                float p = SB[n2*64 + m];
                float2 v = *(const float2*)(V2 + m*68 + d0);
                a0 += p*v.x; a1 += p*v.y;
            }
            CTX[n2*68 + d0]     = a0;
            CTX[n2*68 + d0 + 1] = a1;
        }
        __syncthreads();
    }

    // ---- mo + geo + residual -> h (R1) ----
    load_w_pad(mo_w, W, 4096, 64, 68, tid);
    __syncthreads();
    gemm_mo(CTX, W, mo_b, PF, R1, tid);
    __syncthreads();

    // ---- LayerNorm over C (in place in R1) ----
    {
        int n = tid >> 2, g = tid & 3;
        float* hr = R1 + n*68 + g*16;
        float4 v0 = *(const float4*)(hr);
        float4 v1 = *(const float4*)(hr + 4);
        float4 v2 = *(const float4*)(hr + 8);
        float4 v3 = *(const float4*)(hr + 12);
        float s  = v0.x+v0.y+v0.z+v0.w + v1.x+v1.y+v1.z+v1.w
                 + v2.x+v2.y+v2.z+v2.w + v3.x+v3.y+v3.z+v3.w;
        float s2 = v0.x*v0.x+v0.y*v0.y+v0.z*v0.z+v0.w*v0.w
                 + v1.x*v1.x+v1.y*v1.y+v1.z*v1.z+v1.w*v1.w
                 + v2.x*v2.x+v2.y*v2.y+v2.z*v2.z+v2.w*v2.w
                 + v3.x*v3.x+v3.y*v3.y+v3.z*v3.z+v3.w*v3.w;
        s  += __shfl_xor_sync(0xffffffffu, s, 1);
        s  += __shfl_xor_sync(0xffffffffu, s, 2);
        s2 += __shfl_xor_sync(0xffffffffu, s2, 1);
        s2 += __shfl_xor_sync(0xffffffffu, s2, 2);
        float mu  = s * 0.015625f;
        float var = s2 * 0.015625f - mu*mu;
        float r = rsqrtf(var + 1e-5f);
        int cb = g*16;
        float4 g0 = __ldg((const float4*)(ln_g + cb));
        float4 g1 = __ldg((const float4*)(ln_g + cb + 4));
        float4 g2 = __ldg((const float4*)(ln_g + cb + 8));
        float4 g3 = __ldg((const float4*)(ln_g + cb + 12));
        float4 b0 = __ldg((const float4*)(ln_b + cb));
        float4 b1 = __ldg((const float4*)(ln_b + cb + 4));
        float4 b2 = __ldg((const float4*)(ln_b + cb + 8));
        float4 b3 = __ldg((const float4*)(ln_b + cb + 12));
        hr[0]  = (v0.x-mu)*r*g0.x + b0.x;  hr[1]  = (v0.y-mu)*r*g0.y + b0.y;
        hr[2]  = (v0.z-mu)*r*g0.z + b0.z;  hr[3]  = (v0.w-mu)*r*g0.w + b0.w;
        hr[4]  = (v1.x-mu)*r*g1.x + b1.x;  hr[5]  = (v1.y-mu)*r*g1.y + b1.y;
        hr[6]  = (v1.z-mu)*r*g1.z + b1.z;  hr[7]  = (v1.w-mu)*r*g1.w + b1.w;
        hr[8]  = (v2.x-mu)*r*g2.x + b2.x;  hr[9]  = (v2.y-mu)*r*g2.y + b2.y;
        hr[10] = (v2.z-mu)*r*g2.z + b2.z;  hr[11] = (v2.w-mu)*r*g2.w + b2.w;
        hr[12] = (v3.x-mu)*r*g3.x + b3.x;  hr[13] = (v3.y-mu)*r*g3.y + b3.y;
        hr[14] = (v3.z-mu)*r*g3.z + b3.z;  hr[15] = (v3.w-mu)*r*g3.w + b3.w;
    }
    __syncthreads();

    // ---- output projection + transposed store (stride 65: conflict-free) ----
    load_w_pad(out_w, W, 4096, 64, 68, tid);
    __syncthreads();
    gemm64<64, false>(R1, 68, W, 68, out_b, R3, 65, tid);
    __syncthreads();
    float* og = out + (size_t)b * 4096;
    for (int idx = tid; idx < 4096; idx += NT)
        og[idx] = R3[(idx & 63)*65 + (idx >> 6)];
}

// ---------------- launch ----------------
extern "C" void kernel_launch(void* const* d_in, const int* in_sizes, int n_in,
                              void* d_out, int out_size)
{
    const float* x         = (const float*)d_in[0];
    const float* points    = (const float*)d_in[1];
    const float* conv1_w   = (const float*)d_in[2];
    const float* conv1_b   = (const float*)d_in[3];
    const float* conv2_w   = (const float*)d_in[4];
    const float* conv2_b   = (const float*)d_in[5];
    const float* pattern   = (const float*)d_in[6];
    const float* pm1_w     = (const float*)d_in[7];
    const float* pm1_b     = (const float*)d_in[8];
    const float* pm2_w     = (const float*)d_in[9];
    const float* pm2_b     = (const float*)d_in[10];
    const float* q_w       = (const float*)d_in[11];
    const float* q_b       = (const float*)d_in[12];
    const float* k_w       = (const float*)d_in[13];
    const float* k_b       = (const float*)d_in[14];
    const float* v_w       = (const float*)d_in[15];
    const float* v_b       = (const float*)d_in[16];
    const float* in_w      = (const float*)d_in[17];
    const float* in_b      = (const float*)d_in[18];
    const float* mo_w      = (const float*)d_in[19];
    const float* mo_b      = (const float*)d_in[20];
    const float* out_w     = (const float*)d_in[21];
    const float* out_b     = (const float*)d_in[22];
    const float* ln_g      = (const float*)d_in[23];
    const float* ln_b      = (const float*)d_in[24];
    const int*   adjacency = (const int*)d_in[25];

    int B = in_sizes[0] / 4096;
    size_t smem = SMEM_FLOATS * sizeof(float);
    cudaFuncSetAttribute(esa_main_kernel, cudaFuncAttributeMaxDynamicSharedMemorySize, (int)smem);

    esa_prep_kernel<<<12, NT>>>(points, adjacency, in_w, in_b,
                                q_w, q_b, k_w, k_b, v_w, v_b);
    esa_main_kernel<<<B, NT, smem>>>(x, conv1_w, conv1_b, conv2_w, conv2_b, pattern,
                                     pm1_w, pm1_b, pm2_w, pm2_b, mo_w, mo_b,
                                     out_w, out_b, ln_g, ln_b, (float*)d_out);
}